// round 16
// baseline (speedup 1.0000x reference)
#include <cuda_runtime.h>
#include <cstdint>

#define B_  512
#define C_  6
#define T_  77
#define D_  512
#define LI_ 193

#define OFF_GT 0
#define OFF_GI (B_ * D_)
#define OFF_LT (2 * B_ * D_)
#define OFF_LS (2 * B_ * D_ + B_ * C_ * D_)

// 256-bit read-only load, L2 evict_last (modifier form requires v8.b32)
__device__ __forceinline__ void ldg256(const float* p, float4& a, float4& b) {
    asm("ld.global.nc.L2::evict_last.v8.b32 {%0,%1,%2,%3,%4,%5,%6,%7}, [%8];"
        : "=f"(a.x), "=f"(a.y), "=f"(a.z), "=f"(a.w),
          "=f"(b.x), "=f"(b.y), "=f"(b.z), "=f"(b.w)
        : "l"(p));
}

// 256-bit store, L2 evict_first (outputs are not re-read in the timed loop)
__device__ __forceinline__ void stg256(float* p, const float4& a, const float4& b) {
    asm volatile("st.global.L2::evict_first.v8.b32 [%0], {%1,%2,%3,%4,%5,%6,%7,%8};"
                 :: "l"(p),
                    "f"(a.x), "f"(a.y), "f"(a.z), "f"(a.w),
                    "f"(b.x), "f"(b.y), "f"(b.z), "f"(b.w)
                 : "memory");
}

// Grid = B * 2 CTAs: CTA (b, h) handles d-range [h*256, (h+1)*256).
// 32 threads (1 warp); each thread owns 8 consecutive floats (32 B) of the
// 1024-B row slice and accumulates all 6 channels over all 77 timesteps.
__global__ __launch_bounds__(32, 8)
void clip_fused_kernel(const float* __restrict__ image_features,   // [B, LI, D]
                       const float* __restrict__ text_features,    // [B, T, D]
                       const float* __restrict__ logit_scale,      // [1]
                       const int*   __restrict__ captions,         // [B, T]
                       const int*   __restrict__ noun_chunk_mask,  // [B, C, T]
                       float* __restrict__ out)
{
    const int b   = blockIdx.x >> 1;
    const int h   = blockIdx.x & 1;        // which D-half
    const int tid = threadIdx.x;           // 0..31 -> 8-float column within half

    __shared__ int s_mask[T_];  // bit c set if mask[b,c,t] != 0
    __shared__ int s_val[T_];   // caption values

    // ---- Stage packed noun_chunk_mask + caption values (32 threads, 3 passes) ----
    for (int t = tid; t < T_; t += 32) {
        int pack = 0;
        const int* mrow = noun_chunk_mask + (size_t)b * C_ * T_ + t;
        #pragma unroll
        for (int c = 0; c < C_; ++c)
            if (mrow[c * T_] != 0) pack |= (1 << c);
        s_mask[t] = pack;
        s_val[t]  = captions[(size_t)b * T_ + t];
    }

    // global_image slice = image_features[b, 0, h*256 : (h+1)*256]
    {
        const float* img = image_features + (size_t)b * LI_ * D_ + h * 256 + tid * 8;
        float4 a, c;
        ldg256(img, a, c);
        stg256(out + OFF_GI + (size_t)b * D_ + h * 256 + tid * 8, a, c);
    }
    __syncwarp();   // single warp: masks + caption vals staged

    // ---- Stream all T rows of this D-half slice; accumulate 6 channels ----
    const float* trow = text_features + (size_t)b * T_ * D_ + h * 256 + tid * 8;

    float4 accL[C_], accH[C_];
    #pragma unroll
    for (int c = 0; c < C_; ++c) {
        accL[c] = make_float4(0.f, 0.f, 0.f, 0.f);
        accH[c] = make_float4(0.f, 0.f, 0.f, 0.f);
    }

    // 77 = 11 * 7: unconditional 256-bit loads, unroll 7 keeps 7 independent
    // LDG.256 in flight (1.75 KB/thread). Mask applied AFTER the load as
    // predicated FADDs — never a branch before a load.
    #pragma unroll 7
    for (int t = 0; t < T_; ++t) {
        float4 xl, xh;
        ldg256(trow + (size_t)t * D_, xl, xh);
        const int pack = s_mask[t];
        #pragma unroll
        for (int c = 0; c < C_; ++c) {
            if (pack & (1 << c)) {
                accL[c].x += xl.x; accL[c].y += xl.y;
                accL[c].z += xl.z; accL[c].w += xl.w;
                accH[c].x += xh.x; accH[c].y += xh.y;
                accH[c].z += xh.z; accH[c].w += xh.w;
            }
        }
    }

    // ---- Argmax over captions (single warp, first occurrence on ties) ----
    int eot;
    {
        int v = s_val[tid];
        int i = tid;
        #pragma unroll
        for (int k = 32; k < 96; k += 32) {
            int t = tid + k;
            if (t < T_) {
                int v2 = s_val[t];
                if (v2 > v) { v = v2; i = t; }   // strict > keeps first occurrence
            }
        }
        #pragma unroll
        for (int off = 16; off > 0; off >>= 1) {
            int v2 = __shfl_xor_sync(0xFFFFFFFFu, v, off);
            int i2 = __shfl_xor_sync(0xFFFFFFFFu, i, off);
            if (v2 > v || (v2 == v && i2 < i)) { v = v2; i = i2; }
        }
        eot = __shfl_sync(0xFFFFFFFFu, i, 0);
    }

    // ---- Write local_text for all 6 channels (this D-half slice) ----
    const float inv_T = 1.0f / (float)T_;
    float* lt = out + OFF_LT + (size_t)b * C_ * D_ + h * 256 + tid * 8;
    #pragma unroll
    for (int c = 0; c < C_; ++c) {
        float4 rl, rh;
        rl.x = accL[c].x * inv_T; rl.y = accL[c].y * inv_T;
        rl.z = accL[c].z * inv_T; rl.w = accL[c].w * inv_T;
        rh.x = accH[c].x * inv_T; rh.y = accH[c].y * inv_T;
        rh.z = accH[c].z * inv_T; rh.w = accH[c].w * inv_T;
        stg256(lt + (size_t)c * D_, rl, rh);
    }

    // global_text slice: gather eot row (L1/L2 hot — just streamed)
    {
        float4 ga, gb;
        ldg256(trow + (size_t)eot * D_, ga, gb);
        stg256(out + OFF_GT + (size_t)b * D_ + h * 256 + tid * 8, ga, gb);
    }

    if (blockIdx.x == 0 && tid == 0) {
        out[OFF_LS] = logit_scale[0];
    }
}

extern "C" void kernel_launch(void* const* d_in, const int* in_sizes, int n_in,
                              void* d_out, int out_size)
{
    const float* image_features  = (const float*)d_in[0];
    const float* text_features   = (const float*)d_in[1];
    const float* logit_scale     = (const float*)d_in[2];
    const int*   captions        = (const int*)d_in[3];
    const int*   noun_chunk_mask = (const int*)d_in[4];
    float* out = (float*)d_out;

    clip_fused_kernel<<<B_ * 2, 32>>>(image_features, text_features, logit_scale,
                                      captions, noun_chunk_mask, out);
}

// round 17
// speedup vs baseline: 1.4975x; 1.4975x over previous
#include <cuda_runtime.h>
#include <cstdint>

#define B_  512
#define C_  6
#define T_  77
#define D_  512
#define LI_ 193

#define OFF_GT 0
#define OFF_GI (B_ * D_)
#define OFF_LT (2 * B_ * D_)
#define OFF_LS (2 * B_ * D_ + B_ * C_ * D_)

// read-only 128-bit load with L2 evict_last cache policy (keep resident)
__device__ __forceinline__ float4 ldg_el(const float4* p, uint64_t pol) {
    float4 v;
    asm("ld.global.nc.L2::cache_hint.v4.f32 {%0,%1,%2,%3}, [%4], %5;"
        : "=f"(v.x), "=f"(v.y), "=f"(v.z), "=f"(v.w) : "l"(p), "l"(pol));
    return v;
}

// 128-bit store with L2 evict_first cache policy (outputs not re-read)
__device__ __forceinline__ void stg_ef(float4* p, float4 v, uint64_t pol) {
    asm volatile("st.global.L2::cache_hint.v4.f32 [%0], {%1,%2,%3,%4}, %5;"
                 :: "l"(p), "f"(v.x), "f"(v.y), "f"(v.z), "f"(v.w), "l"(pol)
                 : "memory");
}

// Grid = B * 2 CTAs: CTA (b, h) handles d-range [h*256, (h+1)*256).
// 64 threads; each thread owns one float4 column, accumulates all 6 channels
// over all 77 timesteps. Warp 0 stages masks while warp 1 copies the image
// slice and computes the caption argmax -> eot ready before the single barrier.
__global__ __launch_bounds__(64, 8)
void clip_fused_kernel(const float* __restrict__ image_features,   // [B, LI, D]
                       const float* __restrict__ text_features,    // [B, T, D]
                       const float* __restrict__ logit_scale,      // [1]
                       const int*   __restrict__ captions,         // [B, T]
                       const int*   __restrict__ noun_chunk_mask,  // [B, C, T]
                       float* __restrict__ out)
{
    const int b   = blockIdx.x >> 1;
    const int h   = blockIdx.x & 1;        // which D-half
    const int tid = threadIdx.x;           // 0..63 -> float4 col within half

    __shared__ int s_mask[T_];  // bit c set if mask[b,c,t] != 0
    __shared__ int s_eot;

    uint64_t pol_keep, pol_evict;
    asm("createpolicy.fractional.L2::evict_last.b64 %0, 1.0;"  : "=l"(pol_keep));
    asm("createpolicy.fractional.L2::evict_first.b64 %0, 1.0;" : "=l"(pol_evict));

    if (tid < 32) {
        // ---- Warp 0: stage packed noun_chunk_mask (3 passes) ----
        #pragma unroll
        for (int t = tid; t < T_; t += 32) {
            int pack = 0;
            const int* mrow = noun_chunk_mask + (size_t)b * C_ * T_ + t;
            #pragma unroll
            for (int c = 0; c < C_; ++c)
                if (mrow[c * T_] != 0) pack |= (1 << c);
            s_mask[t] = pack;
        }
    } else {
        // ---- Warp 1: image slice copy + caption argmax ----
        const int lid = tid - 32;
        {
            const float4* img4 = reinterpret_cast<const float4*>(
                image_features + (size_t)b * LI_ * D_) + h * 64;
            // warp 1 copies the full 64-float4 slice: 2 float4 per lane
            float4 g0 = ldg_el(img4 + lid,      pol_keep);
            float4 g1 = ldg_el(img4 + lid + 32, pol_keep);
            float4* gi = reinterpret_cast<float4*>(out + OFF_GI + (size_t)b * D_) + h * 64;
            stg_ef(gi + lid,      g0, pol_evict);
            stg_ef(gi + lid + 32, g1, pol_evict);
        }
        {
            const int* cap = captions + (size_t)b * T_;
            int v = cap[lid];
            int i = lid;
            #pragma unroll
            for (int k = 32; k < 96; k += 32) {
                int t = lid + k;
                if (t < T_) {
                    int v2 = cap[t];
                    if (v2 > v) { v = v2; i = t; }   // strict > keeps first occurrence
                }
            }
            #pragma unroll
            for (int off = 16; off > 0; off >>= 1) {
                int v2 = __shfl_xor_sync(0xFFFFFFFFu, v, off);
                int i2 = __shfl_xor_sync(0xFFFFFFFFu, i, off);
                if (v2 > v || (v2 == v && i2 < i)) { v = v2; i = i2; }
            }
            if (lid == 0) s_eot = i;
        }
    }
    __syncthreads();   // masks + s_eot staged (single barrier)

    // ---- Stream all T rows of this D-half; accumulate 6 channels ----
    const float4* trow = reinterpret_cast<const float4*>(
        text_features + (size_t)b * T_ * D_) + h * 64 + tid;   // stride D/4

    float4 acc[C_];
    #pragma unroll
    for (int c = 0; c < C_; ++c) acc[c] = make_float4(0.f, 0.f, 0.f, 0.f);

    // 77 = 7 * 11: unconditional loads, unroll 11 -> 11 independent LDG.128
    // in flight per iteration. Mask applied AFTER the load as predicated
    // FADDs — never a branch before a load.
    #pragma unroll 11
    for (int t = 0; t < T_; ++t) {
        float4 x = ldg_el(trow + t * (D_ / 4), pol_keep);
        const int pack = s_mask[t];
        #pragma unroll
        for (int c = 0; c < C_; ++c) {
            if (pack & (1 << c)) {
                acc[c].x += x.x; acc[c].y += x.y;
                acc[c].z += x.z; acc[c].w += x.w;
            }
        }
    }

    // ---- Write local_text for all 6 channels (this D-half) ----
    const float inv_T = 1.0f / (float)T_;
    float4* lt = reinterpret_cast<float4*>(out + OFF_LT + (size_t)b * C_ * D_)
                 + h * 64 + tid;
    #pragma unroll
    for (int c = 0; c < C_; ++c) {
        float4 r;
        r.x = acc[c].x * inv_T; r.y = acc[c].y * inv_T;
        r.z = acc[c].z * inv_T; r.w = acc[c].w * inv_T;
        stg_ef(lt + c * (D_ / 4), r, pol_evict);
    }

    // global_text slice: gather eot row (L1/L2 hot — just streamed).
    // s_eot was written before the pre-loop barrier; no extra sync needed.
    {
        float4 g = ldg_el(trow + s_eot * (D_ / 4), pol_keep);
        stg_ef(reinterpret_cast<float4*>(out + OFF_GT + (size_t)b * D_) + h * 64 + tid,
               g, pol_evict);
    }

    if (blockIdx.x == 0 && tid == 0) {
        out[OFF_LS] = logit_scale[0];
    }
}

extern "C" void kernel_launch(void* const* d_in, const int* in_sizes, int n_in,
                              void* d_out, int out_size)
{
    const float* image_features  = (const float*)d_in[0];
    const float* text_features   = (const float*)d_in[1];
    const float* logit_scale     = (const float*)d_in[2];
    const int*   captions        = (const int*)d_in[3];
    const int*   noun_chunk_mask = (const int*)d_in[4];
    float* out = (float*)d_out;

    clip_fused_kernel<<<B_ * 2, 64>>>(image_features, text_features, logit_scale,
                                      captions, noun_chunk_mask, out);
}